// round 6
// baseline (speedup 1.0000x reference)
#include <cuda_runtime.h>
#include <cuda_bf16.h>
#include <cstdint>

#define SCALE_ 0.03125f   // 1/sqrt(1024)

// ---------------- bf16-split scratch (device globals; no allocation) -------
__device__ __nv_bfloat16 g_Xhi[8192*1024];
__device__ __nv_bfloat16 g_Xlo[8192*1024];
__device__ __nv_bfloat16 g_Wqhi[1024*1024];
__device__ __nv_bfloat16 g_Wqlo[1024*1024];
__device__ __nv_bfloat16 g_Wkhi[1024*1024];
__device__ __nv_bfloat16 g_Wklo[1024*1024];
__device__ __nv_bfloat16 g_Wvhi[1024*1024];
__device__ __nv_bfloat16 g_Wvlo[1024*1024];
__device__ __nv_bfloat16 g_Qhi[8192*1024];
__device__ __nv_bfloat16 g_Qlo[8192*1024];
__device__ __nv_bfloat16 g_Khi[8192*1024];
__device__ __nv_bfloat16 g_Klo[8192*1024];
__device__ __nv_bfloat16 g_Vthi[1024*8192];   // V^T: [C, B*N]
__device__ __nv_bfloat16 g_Vtlo[1024*8192];
__device__ __nv_bfloat16 g_AThi[16777216];    // attention split [B,N,N]
__device__ __nv_bfloat16 g_ATlo[16777216];

// ---------------- PTX helpers ----------------------------------------------
__device__ __forceinline__ uint32_t smem_u32(const void* p) {
    uint32_t a;
    asm("{ .reg .u64 t; cvta.to.shared.u64 t, %1; cvt.u32.u64 %0, t; }"
        : "=r"(a) : "l"(p));
    return a;
}

__device__ __forceinline__ void cpa16(uint32_t dst, const void* src) {
    asm volatile("cp.async.cg.shared.global [%0], [%1], 16;" :: "r"(dst), "l"(src));
}
#define CP_COMMIT() asm volatile("cp.async.commit_group;" ::: "memory")

__device__ __forceinline__ void ldm4(uint32_t* r, uint32_t a) {
    asm volatile("ldmatrix.sync.aligned.m8n8.x4.shared.b16 {%0,%1,%2,%3}, [%4];"
        : "=r"(r[0]), "=r"(r[1]), "=r"(r[2]), "=r"(r[3]) : "r"(a));
}

__device__ __forceinline__ void mma16816(float* d, const uint32_t* a,
                                         uint32_t b0, uint32_t b1) {
    asm volatile(
        "mma.sync.aligned.m16n8k16.row.col.f32.bf16.bf16.f32 "
        "{%0,%1,%2,%3}, {%4,%5,%6,%7}, {%8,%9}, {%0,%1,%2,%3};"
        : "+f"(d[0]), "+f"(d[1]), "+f"(d[2]), "+f"(d[3])
        : "r"(a[0]), "r"(a[1]), "r"(a[2]), "r"(a[3]), "r"(b0), "r"(b1));
}

// ---------------- GEMM kernel ----------------------------------------------
// C[m,n] = sum_k A[m,k]*B[n,k]  (NT, 3-pass bf16 split). CTA tile 128x256,
// BK=32, 8 warps (warp tile 64x64, 2x4), 3-stage cp.async, 1 barrier/k-tile.
// MODE 0: out = acc + bias[n] -> bf16 hi/lo
// MODE 1: out = acc + bias[m] -> bf16 hi/lo
// MODE 2/3: out = acc * scale -> fp32
#define BM 128
#define BN 256
#define BKt 32
#define TILE_STRIDE 80                 // bytes per 32-elem bf16 row (+16B pad)
#define SUB_A (128*TILE_STRIDE)        // 10240
#define SUB_B (256*TILE_STRIDE)        // 20480
#define STAGE_BYTES (2*SUB_A + 2*SUB_B)  // Ahi Alo Bhi Blo = 61440
#define GEMM_SMEM (3*STAGE_BYTES)        // 184320 -> 1 CTA/SM

__device__ __forceinline__ void load_tile(
    uint32_t stbase,
    const __nv_bfloat16* pAh, const __nv_bfloat16* pAl,
    const __nv_bfloat16* pBh, const __nv_bfloat16* pBl,
    long long ldA, long long ldB, int k0, int tid)
{
#pragma unroll
    for (int t = 0; t < 2; t++) {           // A: 128 rows x 4 chunks
        int id = tid + t * 256;
        int r = id >> 2, c = id & 3;
        uint32_t doff = (uint32_t)r * TILE_STRIDE + c * 16;
        long long so = (long long)r * ldA + k0 + c * 8;
        cpa16(stbase + doff,         pAh + so);
        cpa16(stbase + SUB_A + doff, pAl + so);
    }
#pragma unroll
    for (int t = 0; t < 4; t++) {           // B: 256 rows x 4 chunks
        int id = tid + t * 256;
        int r = id >> 2, c = id & 3;
        uint32_t doff = (uint32_t)r * TILE_STRIDE + c * 16;
        long long so = (long long)r * ldB + k0 + c * 8;
        cpa16(stbase + 2*SUB_A + doff,         pBh + so);
        cpa16(stbase + 2*SUB_A + SUB_B + doff, pBl + so);
    }
}

template<int MODE>
__global__ __launch_bounds__(256, 1) void mm_kernel(
    const __nv_bfloat16* __restrict__ Ahi, const __nv_bfloat16* __restrict__ Alo,
    long long ldA, long long strideA,
    const __nv_bfloat16* __restrict__ Bhi, const __nv_bfloat16* __restrict__ Blo,
    long long ldB, long long strideB,
    const float* __restrict__ bias,
    float* __restrict__ outF,
    __nv_bfloat16* __restrict__ outHi, __nv_bfloat16* __restrict__ outLo,
    long long ldC, long long strideC,
    int Ksz, float scale)
{
    extern __shared__ char smem[];
    const uint32_t sb = smem_u32(smem);
    const int tid = threadIdx.x;
    const int wid = tid >> 5, lane = tid & 31;
    const int wm = wid >> 2, wn = wid & 3;        // 2 x 4 warp grid, 64x64 tiles
    const int g8 = lane & 7, quad = lane >> 3;
    const int g = lane >> 2, tg = lane & 3;

    const long long bz = blockIdx.z;
    const long long tileM = (long long)blockIdx.y * BM;
    const long long tileN = (long long)blockIdx.x * BN;
    const __nv_bfloat16* pAh = Ahi + bz * strideA + tileM * ldA;
    const __nv_bfloat16* pAl = Alo + bz * strideA + tileM * ldA;
    const __nv_bfloat16* pBh = Bhi + bz * strideB + tileN * ldB;
    const __nv_bfloat16* pBl = Blo + bz * strideB + tileN * ldB;

    float acc[4][8][4];
#pragma unroll
    for (int i = 0; i < 4; i++)
#pragma unroll
        for (int j = 0; j < 8; j++)
#pragma unroll
            for (int c = 0; c < 4; c++) acc[i][j][c] = 0.f;

    const int KT = Ksz / BKt;

    // prologue: 2 of 3 stages in flight
    load_tile(sb + 0*STAGE_BYTES, pAh, pAl, pBh, pBl, ldA, ldB, 0, tid);
    CP_COMMIT();
    load_tile(sb + 1*STAGE_BYTES, pAh, pAl, pBh, pBl, ldA, ldB, BKt, tid);
    CP_COMMIT();

    // per-thread ldmatrix base offsets (row-padded layout, stride 80B)
    const uint32_t aBase = (uint32_t)(wm*64 + g8 + ((quad & 1) ? 8 : 0)) * TILE_STRIDE
                         + ((quad & 2) ? 16 : 0);
    const uint32_t bBase = (uint32_t)(wn*64 + g8 + ((quad & 2) ? 8 : 0)) * TILE_STRIDE
                         + ((quad & 1) ? 16 : 0);

    int stageC = 0;   // stage index of current k-tile
#pragma unroll 1
    for (int kt = 0; kt < KT; kt++) {
        if (kt < KT - 1) asm volatile("cp.async.wait_group 1;" ::: "memory");
        else             asm volatile("cp.async.wait_group 0;" ::: "memory");
        __syncthreads();
        const uint32_t base = sb + stageC * STAGE_BYTES;
        // refill the stage that was consumed at kt-1 (all warps past barrier =>
        // everyone finished reading it). Issued before compute so the loads
        // overlap this k-tile's MMA phase.
        if (kt + 2 < KT) {
            int stageN = stageC + 2; if (stageN >= 3) stageN -= 3;
            load_tile(sb + stageN * STAGE_BYTES, pAh, pAl, pBh, pBl,
                      ldA, ldB, (kt + 2) * BKt, tid);
            CP_COMMIT();
        }
#pragma unroll
        for (int ks = 0; ks < 2; ks++) {
            uint32_t ah[4][4], bh[4][4], tf[4][4];
#pragma unroll
            for (int i = 0; i < 4; i++)
                ldm4(ah[i], base + aBase + i * (16*TILE_STRIDE) + ks * 32);
#pragma unroll
            for (int j = 0; j < 4; j++)
                ldm4(bh[j], base + 2*SUB_A + bBase + j * (16*TILE_STRIDE) + ks * 32);
            // pass 1: hi * hi
#pragma unroll
            for (int i = 0; i < 4; i++)
#pragma unroll
                for (int j = 0; j < 8; j++)
                    mma16816(acc[i][j], ah[i], bh[j>>1][(j&1)*2], bh[j>>1][(j&1)*2+1]);
            // pass 2: hi * lo   (tf = B lo)
#pragma unroll
            for (int j = 0; j < 4; j++)
                ldm4(tf[j], base + 2*SUB_A + SUB_B + bBase + j * (16*TILE_STRIDE) + ks * 32);
#pragma unroll
            for (int i = 0; i < 4; i++)
#pragma unroll
                for (int j = 0; j < 8; j++)
                    mma16816(acc[i][j], ah[i], tf[j>>1][(j&1)*2], tf[j>>1][(j&1)*2+1]);
            // pass 3: lo * hi   (tf = A lo)
#pragma unroll
            for (int i = 0; i < 4; i++)
                ldm4(tf[i], base + SUB_A + aBase + i * (16*TILE_STRIDE) + ks * 32);
#pragma unroll
            for (int i = 0; i < 4; i++)
#pragma unroll
                for (int j = 0; j < 8; j++)
                    mma16816(acc[i][j], tf[i], bh[j>>1][(j&1)*2], bh[j>>1][(j&1)*2+1]);
        }
        if (++stageC == 3) stageC = 0;
    }

    // ---------------- epilogue ----------------
    const long long rowBase = tileM + wm * 64;
    const long long colBase = tileN + wn * 64;
    const long long cOff = bz * strideC;
#pragma unroll
    for (int i = 0; i < 4; i++) {
#pragma unroll
        for (int j = 0; j < 8; j++) {
            long long r0 = rowBase + i * 16 + g;
            long long c0 = colBase + j * 8 + 2 * tg;
#pragma unroll
            for (int h = 0; h < 2; h++) {
                long long r = r0 + h * 8;
                float f0 = acc[i][j][2*h + 0];
                float f1 = acc[i][j][2*h + 1];
                long long off = cOff + r * ldC + c0;
                if (MODE >= 2) {
                    float2 v; v.x = f0 * scale; v.y = f1 * scale;
                    *(float2*)(outF + off) = v;
                } else {
                    if (MODE == 0) { f0 += bias[c0]; f1 += bias[c0 + 1]; }
                    else           { float bb = bias[r]; f0 += bb; f1 += bb; }
                    __nv_bfloat16 h0 = __float2bfloat16(f0);
                    __nv_bfloat16 h1 = __float2bfloat16(f1);
                    __nv_bfloat16 l0 = __float2bfloat16(f0 - __bfloat162float(h0));
                    __nv_bfloat16 l1 = __float2bfloat16(f1 - __bfloat162float(h1));
                    uint32_t hp = (uint32_t)__bfloat16_as_ushort(h0) |
                                  ((uint32_t)__bfloat16_as_ushort(h1) << 16);
                    uint32_t lp = (uint32_t)__bfloat16_as_ushort(l0) |
                                  ((uint32_t)__bfloat16_as_ushort(l1) << 16);
                    *(uint32_t*)(outHi + off) = hp;
                    *(uint32_t*)(outLo + off) = lp;
                }
            }
        }
    }
}

// ---------------- split fp32 -> bf16 hi/lo ---------------------------------
__global__ __launch_bounds__(256) void split_kernel(
    const float4* __restrict__ src, uint2* __restrict__ hi, uint2* __restrict__ lo, int n4)
{
    int i = blockIdx.x * 256 + threadIdx.x;
    if (i >= n4) return;
    float4 v = src[i];
    float f[4] = {v.x, v.y, v.z, v.w};
    uint32_t hh[2], ll[2];
#pragma unroll
    for (int j = 0; j < 2; j++) {
        __nv_bfloat16 h0 = __float2bfloat16(f[2*j]);
        __nv_bfloat16 h1 = __float2bfloat16(f[2*j+1]);
        __nv_bfloat16 l0 = __float2bfloat16(f[2*j]   - __bfloat162float(h0));
        __nv_bfloat16 l1 = __float2bfloat16(f[2*j+1] - __bfloat162float(h1));
        hh[j] = (uint32_t)__bfloat16_as_ushort(h0) | ((uint32_t)__bfloat16_as_ushort(h1) << 16);
        ll[j] = (uint32_t)__bfloat16_as_ushort(l0) | ((uint32_t)__bfloat16_as_ushort(l1) << 16);
    }
    hi[i] = make_uint2(hh[0], hh[1]);
    lo[i] = make_uint2(ll[0], ll[1]);
}

// ---------------- softmax rows, in-place, + bf16 split ---------------------
__global__ __launch_bounds__(256) void softmax_split_kernel(
    float* __restrict__ att, __nv_bfloat16* __restrict__ ahi, __nv_bfloat16* __restrict__ alo)
{
    __shared__ float row[2048];
    __shared__ float red[8];
    const long long base = (long long)blockIdx.x * 2048;
    float* p = att + base;
    const int tid = threadIdx.x;

    float m = -3.0e38f;
    for (int i = tid; i < 2048; i += 256) { float v = p[i]; row[i] = v; m = fmaxf(m, v); }
#pragma unroll
    for (int o = 16; o > 0; o >>= 1) m = fmaxf(m, __shfl_xor_sync(0xffffffffu, m, o));
    if ((tid & 31) == 0) red[tid >> 5] = m;
    __syncthreads();
    m = red[0];
#pragma unroll
    for (int i = 1; i < 8; i++) m = fmaxf(m, red[i]);
    __syncthreads();

    float s = 0.f;
    for (int i = tid; i < 2048; i += 256) { float e = __expf(row[i] - m); row[i] = e; s += e; }
#pragma unroll
    for (int o = 16; o > 0; o >>= 1) s += __shfl_xor_sync(0xffffffffu, s, o);
    if ((tid & 31) == 0) red[tid >> 5] = s;
    __syncthreads();
    s = red[0];
#pragma unroll
    for (int i = 1; i < 8; i++) s += red[i];
    const float inv = 1.f / s;

    for (int i = tid; i < 2048; i += 256) {
        float v = row[i] * inv;
        p[i] = v;
        __nv_bfloat16 h = __float2bfloat16(v);
        ahi[base + i] = h;
        alo[base + i] = __float2bfloat16(v - __bfloat162float(h));
    }
}

// ---------------------------------------------------------------------------
extern "C" void kernel_launch(void* const* d_in, const int* in_sizes, int n_in,
                              void* d_out, int out_size)
{
    const float* X  = (const float*)d_in[0];
    const float* Wq = (const float*)d_in[1];
    const float* bq = (const float*)d_in[2];
    const float* Wk = (const float*)d_in[3];
    const float* bk = (const float*)d_in[4];
    const float* Wv = (const float*)d_in[5];
    const float* bv = (const float*)d_in[6];

    float* outp = (float*)d_out;                      // [4,2048,1024]
    float* att  = outp + 8388608ll;                   // [4,2048,2048]

    __nv_bfloat16 *Xhi, *Xlo, *Wqh, *Wql, *Wkh, *Wkl, *Wvh, *Wvl;
    __nv_bfloat16 *Qhi, *Qlo, *Khi, *Klo, *Vth, *Vtl, *Ahi, *Alo;
    cudaGetSymbolAddress((void**)&Xhi, g_Xhi);  cudaGetSymbolAddress((void**)&Xlo, g_Xlo);
    cudaGetSymbolAddress((void**)&Wqh, g_Wqhi); cudaGetSymbolAddress((void**)&Wql, g_Wqlo);
    cudaGetSymbolAddress((void**)&Wkh, g_Wkhi); cudaGetSymbolAddress((void**)&Wkl, g_Wklo);
    cudaGetSymbolAddress((void**)&Wvh, g_Wvhi); cudaGetSymbolAddress((void**)&Wvl, g_Wvlo);
    cudaGetSymbolAddress((void**)&Qhi, g_Qhi);  cudaGetSymbolAddress((void**)&Qlo, g_Qlo);
    cudaGetSymbolAddress((void**)&Khi, g_Khi);  cudaGetSymbolAddress((void**)&Klo, g_Klo);
    cudaGetSymbolAddress((void**)&Vth, g_Vthi); cudaGetSymbolAddress((void**)&Vtl, g_Vtlo);
    cudaGetSymbolAddress((void**)&Ahi, g_AThi); cudaGetSymbolAddress((void**)&Alo, g_ATlo);

    cudaFuncSetAttribute(mm_kernel<0>, cudaFuncAttributeMaxDynamicSharedMemorySize, GEMM_SMEM);
    cudaFuncSetAttribute(mm_kernel<1>, cudaFuncAttributeMaxDynamicSharedMemorySize, GEMM_SMEM);
    cudaFuncSetAttribute(mm_kernel<2>, cudaFuncAttributeMaxDynamicSharedMemorySize, GEMM_SMEM);
    cudaFuncSetAttribute(mm_kernel<3>, cudaFuncAttributeMaxDynamicSharedMemorySize, GEMM_SMEM);

    // 1) split inputs to bf16 hi/lo
    split_kernel<<<8192, 256>>>((const float4*)X,  (uint2*)Xhi, (uint2*)Xlo, 2097152);
    split_kernel<<<1024, 256>>>((const float4*)Wq, (uint2*)Wqh, (uint2*)Wql, 262144);
    split_kernel<<<1024, 256>>>((const float4*)Wk, (uint2*)Wkh, (uint2*)Wkl, 262144);
    split_kernel<<<1024, 256>>>((const float4*)Wv, (uint2*)Wvh, (uint2*)Wvl, 262144);

    // 2) Q = X Wq^T + bq ; K = X Wk^T + bk   (M=8192, N=1024, K=1024)
    mm_kernel<0><<<dim3(4, 64, 1), 256, GEMM_SMEM>>>(
        Xhi, Xlo, 1024, 0, Wqh, Wql, 1024, 0, bq,
        nullptr, Qhi, Qlo, 1024, 0, 1024, 1.f);
    mm_kernel<0><<<dim3(4, 64, 1), 256, GEMM_SMEM>>>(
        Xhi, Xlo, 1024, 0, Wkh, Wkl, 1024, 0, bk,
        nullptr, Khi, Klo, 1024, 0, 1024, 1.f);

    // 3) V^T = Wv X^T + bv(row)   (M=1024 channels, N=8192 tokens, K=1024)
    mm_kernel<1><<<dim3(32, 8, 1), 256, GEMM_SMEM>>>(
        Wvh, Wvl, 1024, 0, Xhi, Xlo, 1024, 0, bv,
        nullptr, Vth, Vtl, 8192, 0, 1024, 1.f);

    // 4) scores = scale * Q K^T   (per batch: M=N=2048, K=1024) -> att fp32
    mm_kernel<2><<<dim3(8, 16, 4), 256, GEMM_SMEM>>>(
        Qhi, Qlo, 1024, 2097152ll, Khi, Klo, 1024, 2097152ll, nullptr,
        att, nullptr, nullptr, 2048, 4194304ll, 1024, SCALE_);

    // 5) softmax in place + bf16 split of attention
    softmax_split_kernel<<<8192, 256>>>(att, Ahi, Alo);

    // 6) out = att @ V  via  B = V^T  (per batch: M=2048, N=1024, K=2048)
    mm_kernel<3><<<dim3(4, 16, 4), 256, GEMM_SMEM>>>(
        Ahi, Alo, 2048, 4194304ll, Vth, Vtl, 8192, 2048ll, nullptr,
        outp, nullptr, nullptr, 1024, 2097152ll, 2048, 1.f);
}

// round 7
// speedup vs baseline: 1.4784x; 1.4784x over previous
#include <cuda_runtime.h>
#include <cuda_fp16.h>
#include <cstdint>

#define SCALE_ 0.03125f   // 1/sqrt(1024)

// ---------------- fp16-split scratch (device globals; no allocation) -------
__device__ __half g_Xhi[8192*1024];
__device__ __half g_Xlo[8192*1024];
__device__ __half g_Wqhi[1024*1024];
__device__ __half g_Wqlo[1024*1024];
__device__ __half g_Wkhi[1024*1024];
__device__ __half g_Wklo[1024*1024];
__device__ __half g_Wvhi[1024*1024];
__device__ __half g_Wvlo[1024*1024];
__device__ __half g_Qhi[8192*1024];          // Q: hi only (A operand)
__device__ __half g_Khi[8192*1024];
__device__ __half g_Klo[8192*1024];
__device__ __half g_Vthi[1024*8192];          // V^T: [C, B*N]
__device__ __half g_Vtlo[1024*8192];
__device__ __half g_AThi[16777216];           // attention hi [B,N,N] (A operand)

// ---------------- PTX helpers ----------------------------------------------
__device__ __forceinline__ uint32_t smem_u32(const void* p) {
    uint32_t a;
    asm("{ .reg .u64 t; cvta.to.shared.u64 t, %1; cvt.u32.u64 %0, t; }"
        : "=r"(a) : "l"(p));
    return a;
}

__device__ __forceinline__ void cpa16(uint32_t dst, const void* src) {
    asm volatile("cp.async.cg.shared.global [%0], [%1], 16;" :: "r"(dst), "l"(src));
}
#define CP_COMMIT() asm volatile("cp.async.commit_group;" ::: "memory")

__device__ __forceinline__ void ldm4(uint32_t* r, uint32_t a) {
    asm volatile("ldmatrix.sync.aligned.m8n8.x4.shared.b16 {%0,%1,%2,%3}, [%4];"
        : "=r"(r[0]), "=r"(r[1]), "=r"(r[2]), "=r"(r[3]) : "r"(a));
}

__device__ __forceinline__ void mma16816(float* d, const uint32_t* a,
                                         uint32_t b0, uint32_t b1) {
    asm volatile(
        "mma.sync.aligned.m16n8k16.row.col.f32.f16.f16.f32 "
        "{%0,%1,%2,%3}, {%4,%5,%6,%7}, {%8,%9}, {%0,%1,%2,%3};"
        : "+f"(d[0]), "+f"(d[1]), "+f"(d[2]), "+f"(d[3])
        : "r"(a[0]), "r"(a[1]), "r"(a[2]), "r"(a[3]), "r"(b0), "r"(b1));
}

// ---------------- GEMM kernel ----------------------------------------------
// C[m,n] = sum_k A[m,k]*B[n,k]  (NT, fp16 2-pass split: Ah*Bh + Ah*Bl).
// CTA tile 128x128, BK=32, 4 warps (64x64), 3-stage cp.async, 2 CTAs/SM,
// one barrier per k-tile.
// MODE 0: out = acc + bias[n] -> fp16 hi (+lo if outLo)
// MODE 1: out = acc + bias[m] -> fp16 hi/lo
// MODE 2/3: out = acc * scale -> fp32
#define BM 128
#define BN 128
#define BKt 32
#define TILE_STRIDE 80                 // bytes per 32-elem fp16 row (+16B pad)
#define SUB_BYTES (128*TILE_STRIDE)    // 10240
#define STAGE_BYTES (3*SUB_BYTES)      // Ah Bh Bl = 30720
#define GEMM_SMEM (3*STAGE_BYTES)      // 92160 -> 2 CTAs/SM

__device__ __forceinline__ void load_tile(
    uint32_t stbase,
    const __half* pAh, const __half* pBh, const __half* pBl,
    long long ldA, long long ldB, int k0, int tid)
{
#pragma unroll
    for (int t = 0; t < 4; t++) {
        int id = tid + t * 128;
        int r = id >> 2, c = id & 3;
        uint32_t doff = (uint32_t)r * TILE_STRIDE + c * 16;
        long long soA = (long long)r * ldA + k0 + c * 8;
        long long soB = (long long)r * ldB + k0 + c * 8;
        cpa16(stbase + doff,               pAh + soA);
        cpa16(stbase + SUB_BYTES + doff,   pBh + soB);
        cpa16(stbase + 2*SUB_BYTES + doff, pBl + soB);
    }
}

template<int MODE>
__global__ __launch_bounds__(128, 2) void mm_kernel(
    const __half* __restrict__ Ah, long long ldA, long long strideA,
    const __half* __restrict__ Bh, const __half* __restrict__ Bl,
    long long ldB, long long strideB,
    const float* __restrict__ bias,
    float* __restrict__ outF,
    __half* __restrict__ outHi, __half* __restrict__ outLo,
    long long ldC, long long strideC,
    int Ksz, float scale)
{
    extern __shared__ char smem[];
    const uint32_t sb = smem_u32(smem);
    const int tid = threadIdx.x;
    const int wid = tid >> 5, lane = tid & 31;
    const int wm = wid >> 1, wn = wid & 1;        // 2 x 2 warp grid, 64x64 tiles
    const int g8 = lane & 7, quad = lane >> 3;
    const int g = lane >> 2, tg = lane & 3;

    const long long bz = blockIdx.z;
    const long long tileM = (long long)blockIdx.y * BM;
    const long long tileN = (long long)blockIdx.x * BN;
    const __half* pAh = Ah + bz * strideA + tileM * ldA;
    const __half* pBh = Bh + bz * strideB + tileN * ldB;
    const __half* pBl = Bl + bz * strideB + tileN * ldB;

    float acc[4][8][4];
#pragma unroll
    for (int i = 0; i < 4; i++)
#pragma unroll
        for (int j = 0; j < 8; j++)
#pragma unroll
            for (int c = 0; c < 4; c++) acc[i][j][c] = 0.f;

    const int KT = Ksz / BKt;

    // prologue: 2 of 3 stages in flight
    load_tile(sb + 0*STAGE_BYTES, pAh, pBh, pBl, ldA, ldB, 0, tid);
    CP_COMMIT();
    load_tile(sb + 1*STAGE_BYTES, pAh, pBh, pBl, ldA, ldB, BKt, tid);
    CP_COMMIT();

    // per-thread ldmatrix base offsets (row-padded layout, stride 80B)
    const uint32_t aBase = (uint32_t)(wm*64 + g8 + ((quad & 1) ? 8 : 0)) * TILE_STRIDE
                         + ((quad & 2) ? 16 : 0);
    const uint32_t bBase = (uint32_t)(wn*64 + g8 + ((quad & 2) ? 8 : 0)) * TILE_STRIDE
                         + ((quad & 1) ? 16 : 0);

    int stageC = 0;
#pragma unroll 1
    for (int kt = 0; kt < KT; kt++) {
        if (kt < KT - 1) asm volatile("cp.async.wait_group 1;" ::: "memory");
        else             asm volatile("cp.async.wait_group 0;" ::: "memory");
        __syncthreads();
        const uint32_t base = sb + stageC * STAGE_BYTES;
        // refill stage consumed at kt-1; overlaps this k-tile's MMA phase
        if (kt + 2 < KT) {
            int stageN = stageC + 2; if (stageN >= 3) stageN -= 3;
            load_tile(sb + stageN * STAGE_BYTES, pAh, pBh, pBl,
                      ldA, ldB, (kt + 2) * BKt, tid);
            CP_COMMIT();
        }
#pragma unroll
        for (int ks = 0; ks < 2; ks++) {
            uint32_t ah[4][4], bb[4][4];
#pragma unroll
            for (int i = 0; i < 4; i++)
                ldm4(ah[i], base + aBase + i * (16*TILE_STRIDE) + ks * 32);
            // pass 1: Ah * Bh
#pragma unroll
            for (int j = 0; j < 4; j++)
                ldm4(bb[j], base + SUB_BYTES + bBase + j * (16*TILE_STRIDE) + ks * 32);
#pragma unroll
            for (int i = 0; i < 4; i++)
#pragma unroll
                for (int j = 0; j < 8; j++)
                    mma16816(acc[i][j], ah[i], bb[j>>1][(j&1)*2], bb[j>>1][(j&1)*2+1]);
            // pass 2: Ah * Bl
#pragma unroll
            for (int j = 0; j < 4; j++)
                ldm4(bb[j], base + 2*SUB_BYTES + bBase + j * (16*TILE_STRIDE) + ks * 32);
#pragma unroll
            for (int i = 0; i < 4; i++)
#pragma unroll
                for (int j = 0; j < 8; j++)
                    mma16816(acc[i][j], ah[i], bb[j>>1][(j&1)*2], bb[j>>1][(j&1)*2+1]);
        }
        if (++stageC == 3) stageC = 0;
    }

    // ---------------- epilogue ----------------
    const long long rowBase = tileM + wm * 64;
    const long long colBase = tileN + wn * 64;
    const long long cOff = bz * strideC;
#pragma unroll
    for (int i = 0; i < 4; i++) {
#pragma unroll
        for (int j = 0; j < 8; j++) {
            long long r0 = rowBase + i * 16 + g;
            long long c0 = colBase + j * 8 + 2 * tg;
#pragma unroll
            for (int h = 0; h < 2; h++) {
                long long r = r0 + h * 8;
                float f0 = acc[i][j][2*h + 0];
                float f1 = acc[i][j][2*h + 1];
                long long off = cOff + r * ldC + c0;
                if (MODE >= 2) {
                    float2 v; v.x = f0 * scale; v.y = f1 * scale;
                    *(float2*)(outF + off) = v;
                } else {
                    if (MODE == 0) { f0 += bias[c0]; f1 += bias[c0 + 1]; }
                    else           { float bb2 = bias[r]; f0 += bb2; f1 += bb2; }
                    __half h0 = __float2half_rn(f0);
                    __half h1 = __float2half_rn(f1);
                    uint32_t hp = (uint32_t)__half_as_ushort(h0) |
                                  ((uint32_t)__half_as_ushort(h1) << 16);
                    *(uint32_t*)(outHi + off) = hp;
                    if (outLo) {
                        __half l0 = __float2half_rn(f0 - __half2float(h0));
                        __half l1 = __float2half_rn(f1 - __half2float(h1));
                        uint32_t lp = (uint32_t)__half_as_ushort(l0) |
                                      ((uint32_t)__half_as_ushort(l1) << 16);
                        *(uint32_t*)(outLo + off) = lp;
                    }
                }
            }
        }
    }
}

// ---------------- split fp32 -> fp16 hi/lo ---------------------------------
__global__ __launch_bounds__(256) void split_kernel(
    const float4* __restrict__ src, uint2* __restrict__ hi, uint2* __restrict__ lo, int n4)
{
    int i = blockIdx.x * 256 + threadIdx.x;
    if (i >= n4) return;
    float4 v = src[i];
    float f[4] = {v.x, v.y, v.z, v.w};
    uint32_t hh[2], ll[2];
#pragma unroll
    for (int j = 0; j < 2; j++) {
        __half h0 = __float2half_rn(f[2*j]);
        __half h1 = __float2half_rn(f[2*j+1]);
        __half l0 = __float2half_rn(f[2*j]   - __half2float(h0));
        __half l1 = __float2half_rn(f[2*j+1] - __half2float(h1));
        hh[j] = (uint32_t)__half_as_ushort(h0) | ((uint32_t)__half_as_ushort(h1) << 16);
        ll[j] = (uint32_t)__half_as_ushort(l0) | ((uint32_t)__half_as_ushort(l1) << 16);
    }
    hi[i] = make_uint2(hh[0], hh[1]);
    lo[i] = make_uint2(ll[0], ll[1]);
}

// ---------------- softmax rows, in-place, + fp16 hi ------------------------
__global__ __launch_bounds__(256) void softmax_split_kernel(
    float* __restrict__ att, __half* __restrict__ ahi)
{
    __shared__ float row[2048];
    __shared__ float red[8];
    const long long base = (long long)blockIdx.x * 2048;
    float* p = att + base;
    const int tid = threadIdx.x;

    float m = -3.0e38f;
    for (int i = tid; i < 2048; i += 256) { float v = p[i]; row[i] = v; m = fmaxf(m, v); }
#pragma unroll
    for (int o = 16; o > 0; o >>= 1) m = fmaxf(m, __shfl_xor_sync(0xffffffffu, m, o));
    if ((tid & 31) == 0) red[tid >> 5] = m;
    __syncthreads();
    m = red[0];
#pragma unroll
    for (int i = 1; i < 8; i++) m = fmaxf(m, red[i]);
    __syncthreads();

    float s = 0.f;
    for (int i = tid; i < 2048; i += 256) { float e = __expf(row[i] - m); row[i] = e; s += e; }
#pragma unroll
    for (int o = 16; o > 0; o >>= 1) s += __shfl_xor_sync(0xffffffffu, s, o);
    if ((tid & 31) == 0) red[tid >> 5] = s;
    __syncthreads();
    s = red[0];
#pragma unroll
    for (int i = 1; i < 8; i++) s += red[i];
    const float inv = 1.f / s;

    for (int i = tid; i < 2048; i += 256) {
        float v = row[i] * inv;
        p[i] = v;
        ahi[base + i] = __float2half_rn(v);
    }
}

// ---------------------------------------------------------------------------
extern "C" void kernel_launch(void* const* d_in, const int* in_sizes, int n_in,
                              void* d_out, int out_size)
{
    const float* X  = (const float*)d_in[0];
    const float* Wq = (const float*)d_in[1];
    const float* bq = (const float*)d_in[2];
    const float* Wk = (const float*)d_in[3];
    const float* bk = (const float*)d_in[4];
    const float* Wv = (const float*)d_in[5];
    const float* bv = (const float*)d_in[6];

    float* outp = (float*)d_out;                      // [4,2048,1024]
    float* att  = outp + 8388608ll;                   // [4,2048,2048]

    __half *Xhi, *Xlo, *Wqh, *Wql, *Wkh, *Wkl, *Wvh, *Wvl;
    __half *Qhi, *Khi, *Klo, *Vth, *Vtl, *Ahi;
    cudaGetSymbolAddress((void**)&Xhi, g_Xhi);  cudaGetSymbolAddress((void**)&Xlo, g_Xlo);
    cudaGetSymbolAddress((void**)&Wqh, g_Wqhi); cudaGetSymbolAddress((void**)&Wql, g_Wqlo);
    cudaGetSymbolAddress((void**)&Wkh, g_Wkhi); cudaGetSymbolAddress((void**)&Wkl, g_Wklo);
    cudaGetSymbolAddress((void**)&Wvh, g_Wvhi); cudaGetSymbolAddress((void**)&Wvl, g_Wvlo);
    cudaGetSymbolAddress((void**)&Qhi, g_Qhi);
    cudaGetSymbolAddress((void**)&Khi, g_Khi);  cudaGetSymbolAddress((void**)&Klo, g_Klo);
    cudaGetSymbolAddress((void**)&Vth, g_Vthi); cudaGetSymbolAddress((void**)&Vtl, g_Vtlo);
    cudaGetSymbolAddress((void**)&Ahi, g_AThi);

    cudaFuncSetAttribute(mm_kernel<0>, cudaFuncAttributeMaxDynamicSharedMemorySize, GEMM_SMEM);
    cudaFuncSetAttribute(mm_kernel<1>, cudaFuncAttributeMaxDynamicSharedMemorySize, GEMM_SMEM);
    cudaFuncSetAttribute(mm_kernel<2>, cudaFuncAttributeMaxDynamicSharedMemorySize, GEMM_SMEM);
    cudaFuncSetAttribute(mm_kernel<3>, cudaFuncAttributeMaxDynamicSharedMemorySize, GEMM_SMEM);

    // 1) split inputs to fp16 hi/lo
    split_kernel<<<8192, 256>>>((const float4*)X,  (uint2*)Xhi, (uint2*)Xlo, 2097152);
    split_kernel<<<1024, 256>>>((const float4*)Wq, (uint2*)Wqh, (uint2*)Wql, 262144);
    split_kernel<<<1024, 256>>>((const float4*)Wk, (uint2*)Wkh, (uint2*)Wkl, 262144);
    split_kernel<<<1024, 256>>>((const float4*)Wv, (uint2*)Wvh, (uint2*)Wvl, 262144);

    // 2) Q = X Wq^T + bq (hi only) ; K = X Wk^T + bk (hi+lo)
    mm_kernel<0><<<dim3(8, 64, 1), 128, GEMM_SMEM>>>(
        Xhi, 1024, 0, Wqh, Wql, 1024, 0, bq,
        nullptr, Qhi, nullptr, 1024, 0, 1024, 1.f);
    mm_kernel<0><<<dim3(8, 64, 1), 128, GEMM_SMEM>>>(
        Xhi, 1024, 0, Wkh, Wkl, 1024, 0, bk,
        nullptr, Khi, Klo, 1024, 0, 1024, 1.f);

    // 3) V^T = Wv X^T + bv(row)   (M=1024 channels, N=8192 tokens, K=1024)
    mm_kernel<1><<<dim3(64, 8, 1), 128, GEMM_SMEM>>>(
        Wvh, 1024, 0, Xhi, Xlo, 1024, 0, bv,
        nullptr, Vth, Vtl, 8192, 0, 1024, 1.f);

    // 4) scores = scale * Q K^T   (per batch: M=N=2048, K=1024) -> att fp32
    mm_kernel<2><<<dim3(16, 16, 4), 128, GEMM_SMEM>>>(
        Qhi, 1024, 2097152ll, Khi, Klo, 1024, 2097152ll, nullptr,
        att, nullptr, nullptr, 2048, 4194304ll, 1024, SCALE_);

    // 5) softmax in place + fp16 hi of attention
    softmax_split_kernel<<<8192, 256>>>(att, Ahi);

    // 6) out = att @ V  via  B = V^T  (per batch: M=2048, N=1024, K=2048)
    mm_kernel<3><<<dim3(8, 16, 4), 128, GEMM_SMEM>>>(
        Ahi, 2048, 4194304ll, Vth, Vtl, 8192, 2048ll, nullptr,
        outp, nullptr, nullptr, 1024, 2097152ll, 2048, 1.f);
}

// round 8
// speedup vs baseline: 1.5637x; 1.0577x over previous
#include <cuda_runtime.h>
#include <cuda_fp16.h>
#include <cstdint>

#define SCALE_ 0.03125f   // 1/sqrt(1024)

// ---------------- fp16-split scratch (device globals; no allocation) -------
__device__ __half g_Xhi[8192*1024];
__device__ __half g_Xlo[8192*1024];
__device__ __half g_Wqhi[1024*1024];
__device__ __half g_Wqlo[1024*1024];
__device__ __half g_Wkhi[1024*1024];
__device__ __half g_Wklo[1024*1024];
__device__ __half g_Wvhi[1024*1024];
__device__ __half g_Wvlo[1024*1024];
__device__ __half g_Qhi[8192*1024];          // Q: hi only (A operand)
__device__ __half g_Khi[8192*1024];
__device__ __half g_Klo[8192*1024];
__device__ __half g_Vthi[1024*8192];          // V^T: [C, B*N]
__device__ __half g_Vtlo[1024*8192];
__device__ __half g_AThi[16777216];           // attention hi [B,N,N] (A operand)

// ---------------- stream/event infra (created at load, before checkpoints) -
static cudaStream_t gsK, gsV;        // zero-init -> default stream fallback
static cudaEvent_t  geX, geK, geV;
namespace {
struct StreamInit {
    StreamInit() {
        cudaStreamCreateWithFlags(&gsK, cudaStreamNonBlocking);
        cudaStreamCreateWithFlags(&gsV, cudaStreamNonBlocking);
        cudaEventCreateWithFlags(&geX, cudaEventDisableTiming);
        cudaEventCreateWithFlags(&geK, cudaEventDisableTiming);
        cudaEventCreateWithFlags(&geV, cudaEventDisableTiming);
    }
};
static StreamInit g_si;
}

// ---------------- PTX helpers ----------------------------------------------
__device__ __forceinline__ uint32_t smem_u32(const void* p) {
    uint32_t a;
    asm("{ .reg .u64 t; cvta.to.shared.u64 t, %1; cvt.u32.u64 %0, t; }"
        : "=r"(a) : "l"(p));
    return a;
}

__device__ __forceinline__ void cpa16(uint32_t dst, const void* src) {
    asm volatile("cp.async.cg.shared.global [%0], [%1], 16;" :: "r"(dst), "l"(src));
}
#define CP_COMMIT() asm volatile("cp.async.commit_group;" ::: "memory")

__device__ __forceinline__ void ldm4(uint32_t* r, uint32_t a) {
    asm volatile("ldmatrix.sync.aligned.m8n8.x4.shared.b16 {%0,%1,%2,%3}, [%4];"
        : "=r"(r[0]), "=r"(r[1]), "=r"(r[2]), "=r"(r[3]) : "r"(a));
}

__device__ __forceinline__ void mma16816(float* d, const uint32_t* a,
                                         uint32_t b0, uint32_t b1) {
    asm volatile(
        "mma.sync.aligned.m16n8k16.row.col.f32.f16.f16.f32 "
        "{%0,%1,%2,%3}, {%4,%5,%6,%7}, {%8,%9}, {%0,%1,%2,%3};"
        : "+f"(d[0]), "+f"(d[1]), "+f"(d[2]), "+f"(d[3])
        : "r"(a[0]), "r"(a[1]), "r"(a[2]), "r"(a[3]), "r"(b0), "r"(b1));
}

// ---------------- GEMM kernel (identical math to R7) ------------------------
#define BM 128
#define BN 128
#define BKt 32
#define TILE_STRIDE 80                 // bytes per 32-elem fp16 row (+16B pad)
#define SUB_BYTES (128*TILE_STRIDE)    // 10240
#define STAGE_BYTES (3*SUB_BYTES)      // Ah Bh Bl = 30720
#define GEMM_SMEM (3*STAGE_BYTES)      // 92160 -> 2 CTAs/SM

__device__ __forceinline__ void load_tile(
    uint32_t stbase,
    const __half* pAh, const __half* pBh, const __half* pBl,
    long long ldA, long long ldB, int k0, int tid)
{
#pragma unroll
    for (int t = 0; t < 4; t++) {
        int id = tid + t * 128;
        int r = id >> 2, c = id & 3;
        uint32_t doff = (uint32_t)r * TILE_STRIDE + c * 16;
        long long soA = (long long)r * ldA + k0 + c * 8;
        long long soB = (long long)r * ldB + k0 + c * 8;
        cpa16(stbase + doff,               pAh + soA);
        cpa16(stbase + SUB_BYTES + doff,   pBh + soB);
        cpa16(stbase + 2*SUB_BYTES + doff, pBl + soB);
    }
}

template<int MODE>
__global__ __launch_bounds__(128, 2) void mm_kernel(
    const __half* __restrict__ Ah, long long ldA, long long strideA,
    const __half* __restrict__ Bh, const __half* __restrict__ Bl,
    long long ldB, long long strideB,
    const float* __restrict__ bias,
    float* __restrict__ outF,
    __half* __restrict__ outHi, __half* __restrict__ outLo,
    long long ldC, long long strideC,
    int Ksz, float scale)
{
    extern __shared__ char smem[];
    const uint32_t sb = smem_u32(smem);
    const int tid = threadIdx.x;
    const int wid = tid >> 5, lane = tid & 31;
    const int wm = wid >> 1, wn = wid & 1;        // 2 x 2 warp grid, 64x64 tiles
    const int g8 = lane & 7, quad = lane >> 3;
    const int g = lane >> 2, tg = lane & 3;

    const long long bz = blockIdx.z;
    const long long tileM = (long long)blockIdx.y * BM;
    const long long tileN = (long long)blockIdx.x * BN;
    const __half* pAh = Ah + bz * strideA + tileM * ldA;
    const __half* pBh = Bh + bz * strideB + tileN * ldB;
    const __half* pBl = Bl + bz * strideB + tileN * ldB;

    float acc[4][8][4];
#pragma unroll
    for (int i = 0; i < 4; i++)
#pragma unroll
        for (int j = 0; j < 8; j++)
#pragma unroll
            for (int c = 0; c < 4; c++) acc[i][j][c] = 0.f;

    const int KT = Ksz / BKt;

    // prologue: 2 of 3 stages in flight
    load_tile(sb + 0*STAGE_BYTES, pAh, pBh, pBl, ldA, ldB, 0, tid);
    CP_COMMIT();
    load_tile(sb + 1*STAGE_BYTES, pAh, pBh, pBl, ldA, ldB, BKt, tid);
    CP_COMMIT();

    const uint32_t aBase = (uint32_t)(wm*64 + g8 + ((quad & 1) ? 8 : 0)) * TILE_STRIDE
                         + ((quad & 2) ? 16 : 0);
    const uint32_t bBase = (uint32_t)(wn*64 + g8 + ((quad & 2) ? 8 : 0)) * TILE_STRIDE
                         + ((quad & 1) ? 16 : 0);

    int stageC = 0;
#pragma unroll 1
    for (int kt = 0; kt < KT; kt++) {
        if (kt < KT - 1) asm volatile("cp.async.wait_group 1;" ::: "memory");
        else             asm volatile("cp.async.wait_group 0;" ::: "memory");
        __syncthreads();
        const uint32_t base = sb + stageC * STAGE_BYTES;
        if (kt + 2 < KT) {
            int stageN = stageC + 2; if (stageN >= 3) stageN -= 3;
            load_tile(sb + stageN * STAGE_BYTES, pAh, pBh, pBl,
                      ldA, ldB, (kt + 2) * BKt, tid);
            CP_COMMIT();
        }
#pragma unroll
        for (int ks = 0; ks < 2; ks++) {
            uint32_t ah[4][4], bb[4][4];
#pragma unroll
            for (int i = 0; i < 4; i++)
                ldm4(ah[i], base + aBase + i * (16*TILE_STRIDE) + ks * 32);
            // pass 1: Ah * Bh
#pragma unroll
            for (int j = 0; j < 4; j++)
                ldm4(bb[j], base + SUB_BYTES + bBase + j * (16*TILE_STRIDE) + ks * 32);
#pragma unroll
            for (int i = 0; i < 4; i++)
#pragma unroll
                for (int j = 0; j < 8; j++)
                    mma16816(acc[i][j], ah[i], bb[j>>1][(j&1)*2], bb[j>>1][(j&1)*2+1]);
            // pass 2: Ah * Bl
#pragma unroll
            for (int j = 0; j < 4; j++)
                ldm4(bb[j], base + 2*SUB_BYTES + bBase + j * (16*TILE_STRIDE) + ks * 32);
#pragma unroll
            for (int i = 0; i < 4; i++)
#pragma unroll
                for (int j = 0; j < 8; j++)
                    mma16816(acc[i][j], ah[i], bb[j>>1][(j&1)*2], bb[j>>1][(j&1)*2+1]);
        }
        if (++stageC == 3) stageC = 0;
    }

    // ---------------- epilogue ----------------
    const long long rowBase = tileM + wm * 64;
    const long long colBase = tileN + wn * 64;
    const long long cOff = bz * strideC;
#pragma unroll
    for (int i = 0; i < 4; i++) {
#pragma unroll
        for (int j = 0; j < 8; j++) {
            long long r0 = rowBase + i * 16 + g;
            long long c0 = colBase + j * 8 + 2 * tg;
#pragma unroll
            for (int h = 0; h < 2; h++) {
                long long r = r0 + h * 8;
                float f0 = acc[i][j][2*h + 0];
                float f1 = acc[i][j][2*h + 1];
                long long off = cOff + r * ldC + c0;
                if (MODE >= 2) {
                    float2 v; v.x = f0 * scale; v.y = f1 * scale;
                    *(float2*)(outF + off) = v;
                } else {
                    if (MODE == 0) { f0 += bias[c0]; f1 += bias[c0 + 1]; }
                    else           { float bb2 = bias[r]; f0 += bb2; f1 += bb2; }
                    __half h0 = __float2half_rn(f0);
                    __half h1 = __float2half_rn(f1);
                    uint32_t hp = (uint32_t)__half_as_ushort(h0) |
                                  ((uint32_t)__half_as_ushort(h1) << 16);
                    *(uint32_t*)(outHi + off) = hp;
                    if (outLo) {
                        __half l0 = __float2half_rn(f0 - __half2float(h0));
                        __half l1 = __float2half_rn(f1 - __half2float(h1));
                        uint32_t lp = (uint32_t)__half_as_ushort(l0) |
                                      ((uint32_t)__half_as_ushort(l1) << 16);
                        *(uint32_t*)(outLo + off) = lp;
                    }
                }
            }
        }
    }
}

// ---------------- split fp32 -> fp16 hi/lo ---------------------------------
__global__ __launch_bounds__(256) void split_kernel(
    const float4* __restrict__ src, uint2* __restrict__ hi, uint2* __restrict__ lo, int n4)
{
    int i = blockIdx.x * 256 + threadIdx.x;
    if (i >= n4) return;
    float4 v = src[i];
    float f[4] = {v.x, v.y, v.z, v.w};
    uint32_t hh[2], ll[2];
#pragma unroll
    for (int j = 0; j < 2; j++) {
        __half h0 = __float2half_rn(f[2*j]);
        __half h1 = __float2half_rn(f[2*j+1]);
        __half l0 = __float2half_rn(f[2*j]   - __half2float(h0));
        __half l1 = __float2half_rn(f[2*j+1] - __half2float(h1));
        hh[j] = (uint32_t)__half_as_ushort(h0) | ((uint32_t)__half_as_ushort(h1) << 16);
        ll[j] = (uint32_t)__half_as_ushort(l0) | ((uint32_t)__half_as_ushort(l1) << 16);
    }
    hi[i] = make_uint2(hh[0], hh[1]);
    lo[i] = make_uint2(ll[0], ll[1]);
}

// ---------------- softmax rows, in-place, + fp16 hi ------------------------
__global__ __launch_bounds__(256) void softmax_split_kernel(
    float* __restrict__ att, __half* __restrict__ ahi)
{
    __shared__ float row[2048];
    __shared__ float red[8];
    const long long base = (long long)blockIdx.x * 2048;
    float* p = att + base;
    const int tid = threadIdx.x;

    float m = -3.0e38f;
    for (int i = tid; i < 2048; i += 256) { float v = p[i]; row[i] = v; m = fmaxf(m, v); }
#pragma unroll
    for (int o = 16; o > 0; o >>= 1) m = fmaxf(m, __shfl_xor_sync(0xffffffffu, m, o));
    if ((tid & 31) == 0) red[tid >> 5] = m;
    __syncthreads();
    m = red[0];
#pragma unroll
    for (int i = 1; i < 8; i++) m = fmaxf(m, red[i]);
    __syncthreads();

    float s = 0.f;
    for (int i = tid; i < 2048; i += 256) { float e = __expf(row[i] - m); row[i] = e; s += e; }
#pragma unroll
    for (int o = 16; o > 0; o >>= 1) s += __shfl_xor_sync(0xffffffffu, s, o);
    if ((tid & 31) == 0) red[tid >> 5] = s;
    __syncthreads();
    s = red[0];
#pragma unroll
    for (int i = 1; i < 8; i++) s += red[i];
    const float inv = 1.f / s;

    for (int i = tid; i < 2048; i += 256) {
        float v = row[i] * inv;
        p[i] = v;
        ahi[base + i] = __float2half_rn(v);
    }
}

// ---------------------------------------------------------------------------
extern "C" void kernel_launch(void* const* d_in, const int* in_sizes, int n_in,
                              void* d_out, int out_size)
{
    const float* X  = (const float*)d_in[0];
    const float* Wq = (const float*)d_in[1];
    const float* bq = (const float*)d_in[2];
    const float* Wk = (const float*)d_in[3];
    const float* bk = (const float*)d_in[4];
    const float* Wv = (const float*)d_in[5];
    const float* bv = (const float*)d_in[6];

    float* outp = (float*)d_out;                      // [4,2048,1024]
    float* att  = outp + 8388608ll;                   // [4,2048,2048]

    __half *Xhi, *Xlo, *Wqh, *Wql, *Wkh, *Wkl, *Wvh, *Wvl;
    __half *Qhi, *Khi, *Klo, *Vth, *Vtl, *Ahi;
    cudaGetSymbolAddress((void**)&Xhi, g_Xhi);  cudaGetSymbolAddress((void**)&Xlo, g_Xlo);
    cudaGetSymbolAddress((void**)&Wqh, g_Wqhi); cudaGetSymbolAddress((void**)&Wql, g_Wqlo);
    cudaGetSymbolAddress((void**)&Wkh, g_Wkhi); cudaGetSymbolAddress((void**)&Wkl, g_Wklo);
    cudaGetSymbolAddress((void**)&Wvh, g_Wvhi); cudaGetSymbolAddress((void**)&Wvl, g_Wvlo);
    cudaGetSymbolAddress((void**)&Qhi, g_Qhi);
    cudaGetSymbolAddress((void**)&Khi, g_Khi);  cudaGetSymbolAddress((void**)&Klo, g_Klo);
    cudaGetSymbolAddress((void**)&Vth, g_Vthi); cudaGetSymbolAddress((void**)&Vtl, g_Vtlo);
    cudaGetSymbolAddress((void**)&Ahi, g_AThi);

    cudaFuncSetAttribute(mm_kernel<0>, cudaFuncAttributeMaxDynamicSharedMemorySize, GEMM_SMEM);
    cudaFuncSetAttribute(mm_kernel<1>, cudaFuncAttributeMaxDynamicSharedMemorySize, GEMM_SMEM);
    cudaFuncSetAttribute(mm_kernel<2>, cudaFuncAttributeMaxDynamicSharedMemorySize, GEMM_SMEM);
    cudaFuncSetAttribute(mm_kernel<3>, cudaFuncAttributeMaxDynamicSharedMemorySize, GEMM_SMEM);

    const cudaStream_t s0 = 0;
    const cudaStream_t sK = gsK;   // zero-init fallback = default stream (serial, correct)
    const cudaStream_t sV = gsV;

    // ---- main stream: split X, then fork ----
    split_kernel<<<8192, 256, 0, s0>>>((const float4*)X, (uint2*)Xhi, (uint2*)Xlo, 2097152);
    cudaEventRecord(geX, s0);

    // ---- branch K ----
    cudaStreamWaitEvent(sK, geX, 0);
    split_kernel<<<1024, 256, 0, sK>>>((const float4*)Wk, (uint2*)Wkh, (uint2*)Wkl, 262144);
    mm_kernel<0><<<dim3(8, 64, 1), 128, GEMM_SMEM, sK>>>(
        Xhi, 1024, 0, Wkh, Wkl, 1024, 0, bk,
        nullptr, Khi, Klo, 1024, 0, 1024, 1.f);
    cudaEventRecord(geK, sK);

    // ---- branch V ----
    cudaStreamWaitEvent(sV, geX, 0);
    split_kernel<<<1024, 256, 0, sV>>>((const float4*)Wv, (uint2*)Wvh, (uint2*)Wvl, 262144);
    mm_kernel<1><<<dim3(64, 8, 1), 128, GEMM_SMEM, sV>>>(
        Wvh, 1024, 0, Xhi, Xlo, 1024, 0, bv,
        nullptr, Vth, Vtl, 8192, 0, 1024, 1.f);
    cudaEventRecord(geV, sV);

    // ---- main stream: Q proj ----
    split_kernel<<<1024, 256, 0, s0>>>((const float4*)Wq, (uint2*)Wqh, (uint2*)Wql, 262144);
    mm_kernel<0><<<dim3(8, 64, 1), 128, GEMM_SMEM, s0>>>(
        Xhi, 1024, 0, Wqh, Wql, 1024, 0, bq,
        nullptr, Qhi, nullptr, 1024, 0, 1024, 1.f);

    // ---- scores = scale * Q K^T (needs K branch) ----
    cudaStreamWaitEvent(s0, geK, 0);
    mm_kernel<2><<<dim3(16, 16, 4), 128, GEMM_SMEM, s0>>>(
        Qhi, 1024, 2097152ll, Khi, Klo, 1024, 2097152ll, nullptr,
        att, nullptr, nullptr, 2048, 4194304ll, 1024, SCALE_);

    // ---- softmax in place + fp16 hi of attention ----
    softmax_split_kernel<<<8192, 256, 0, s0>>>(att, Ahi);

    // ---- out = att @ V (needs V branch) ----
    cudaStreamWaitEvent(s0, geV, 0);
    mm_kernel<3><<<dim3(8, 16, 4), 128, GEMM_SMEM, s0>>>(
        Ahi, 2048, 4194304ll, Vth, Vtl, 8192, 2048ll, nullptr,
        outp, nullptr, nullptr, 1024, 2097152ll, 2048, 1.f);
}

// round 9
// speedup vs baseline: 1.9198x; 1.2278x over previous
#include <cuda_runtime.h>
#include <cuda_fp16.h>
#include <cstdint>

#define SCALE_ 0.03125f   // 1/sqrt(1024)

// ---------------- fp16-split scratch (device globals; no allocation) -------
__device__ __half g_Xhi[8192*1024];
__device__ __half g_Xlo[8192*1024];
__device__ __half g_Wqhi[1024*1024];
__device__ __half g_Wqlo[1024*1024];
__device__ __half g_Wkhi[1024*1024];
__device__ __half g_Wklo[1024*1024];
__device__ __half g_Wvhi[1024*1024];
__device__ __half g_Wvlo[1024*1024];
__device__ __half g_Qhi[8192*1024];          // Q: hi only (A operand)
__device__ __half g_Khi[8192*1024];
__device__ __half g_Klo[8192*1024];
__device__ __half g_Vthi[1024*8192];          // V^T hi: [C, B*N]
__device__ __half g_AThi[16777216];           // attention hi [B,N,N] (A operand)

// ---------------- stream/event infra (created at load, before checkpoints) -
static cudaStream_t gsK, gsV, gs3;   // zero-init -> default stream fallback
static cudaEvent_t  geX, geQ, geK, geV, geB1, geB2, geB3;
namespace {
struct StreamInit {
    StreamInit() {
        cudaStreamCreateWithFlags(&gsK, cudaStreamNonBlocking);
        cudaStreamCreateWithFlags(&gsV, cudaStreamNonBlocking);
        cudaStreamCreateWithFlags(&gs3, cudaStreamNonBlocking);
        cudaEventCreateWithFlags(&geX, cudaEventDisableTiming);
        cudaEventCreateWithFlags(&geQ, cudaEventDisableTiming);
        cudaEventCreateWithFlags(&geK, cudaEventDisableTiming);
        cudaEventCreateWithFlags(&geV, cudaEventDisableTiming);
        cudaEventCreateWithFlags(&geB1, cudaEventDisableTiming);
        cudaEventCreateWithFlags(&geB2, cudaEventDisableTiming);
        cudaEventCreateWithFlags(&geB3, cudaEventDisableTiming);
    }
};
static StreamInit g_si;
}

// ---------------- PTX helpers ----------------------------------------------
__device__ __forceinline__ uint32_t smem_u32(const void* p) {
    uint32_t a;
    asm("{ .reg .u64 t; cvta.to.shared.u64 t, %1; cvt.u32.u64 %0, t; }"
        : "=r"(a) : "l"(p));
    return a;
}

__device__ __forceinline__ void cpa16(uint32_t dst, const void* src) {
    asm volatile("cp.async.cg.shared.global [%0], [%1], 16;" :: "r"(dst), "l"(src));
}
#define CP_COMMIT() asm volatile("cp.async.commit_group;" ::: "memory")

__device__ __forceinline__ void ldm4(uint32_t* r, uint32_t a) {
    asm volatile("ldmatrix.sync.aligned.m8n8.x4.shared.b16 {%0,%1,%2,%3}, [%4];"
        : "=r"(r[0]), "=r"(r[1]), "=r"(r[2]), "=r"(r[3]) : "r"(a));
}

__device__ __forceinline__ void mma16816(float* d, const uint32_t* a,
                                         uint32_t b0, uint32_t b1) {
    asm volatile(
        "mma.sync.aligned.m16n8k16.row.col.f32.f16.f16.f32 "
        "{%0,%1,%2,%3}, {%4,%5,%6,%7}, {%8,%9}, {%0,%1,%2,%3};"
        : "+f"(d[0]), "+f"(d[1]), "+f"(d[2]), "+f"(d[3])
        : "r"(a[0]), "r"(a[1]), "r"(a[2]), "r"(a[3]), "r"(b0), "r"(b1));
}

// ---------------- GEMM kernel ----------------------------------------------
// C[m,n] = sum_k A[m,k]*B[n,k]  (NT, fp16 split).
// NPASS=2: acc = Ah*Bh + Ah*Bl.  NPASS=1: acc = Ah*Bh.
// CTA tile 128x128, BK=32, 4 warps (64x64), 3-stage cp.async, 2 CTAs/SM.
// MODE 0: out = acc + bias[n] -> fp16 hi (+lo if outLo)
// MODE 1: out = acc + bias[m] -> fp16 hi (+lo if outLo)
// MODE 2/3: out = acc * scale -> fp32
#define BM 128
#define BN 128
#define BKt 32
#define TILE_STRIDE 80                 // bytes per 32-elem fp16 row (+16B pad)
#define SUB_BYTES (128*TILE_STRIDE)    // 10240
#define SMEM_P2 (3*3*SUB_BYTES)        // 92160 (Ah Bh Bl x 3 stages)
#define SMEM_P1 (3*2*SUB_BYTES)        // 61440 (Ah Bh    x 3 stages)

template<int NPASS>
__device__ __forceinline__ void load_tile(
    uint32_t stbase,
    const __half* pAh, const __half* pBh, const __half* pBl,
    long long ldA, long long ldB, int k0, int tid)
{
#pragma unroll
    for (int t = 0; t < 4; t++) {
        int id = tid + t * 128;
        int r = id >> 2, c = id & 3;
        uint32_t doff = (uint32_t)r * TILE_STRIDE + c * 16;
        long long soA = (long long)r * ldA + k0 + c * 8;
        long long soB = (long long)r * ldB + k0 + c * 8;
        cpa16(stbase + doff,               pAh + soA);
        cpa16(stbase + SUB_BYTES + doff,   pBh + soB);
        if (NPASS == 2) cpa16(stbase + 2*SUB_BYTES + doff, pBl + soB);
    }
}

template<int MODE, int NPASS>
__global__ __launch_bounds__(128, 2) void mm_kernel(
    const __half* __restrict__ Ah, long long ldA, long long strideA,
    const __half* __restrict__ Bh, const __half* __restrict__ Bl,
    long long ldB, long long strideB,
    const float* __restrict__ bias,
    float* __restrict__ outF,
    __half* __restrict__ outHi, __half* __restrict__ outLo,
    long long ldC, long long strideC,
    int Ksz, float scale)
{
    constexpr uint32_t STB = (uint32_t)((1 + NPASS) * SUB_BYTES);
    extern __shared__ char smem[];
    const uint32_t sb = smem_u32(smem);
    const int tid = threadIdx.x;
    const int wid = tid >> 5, lane = tid & 31;
    const int wm = wid >> 1, wn = wid & 1;        // 2 x 2 warp grid, 64x64 tiles
    const int g8 = lane & 7, quad = lane >> 3;
    const int g = lane >> 2, tg = lane & 3;

    const long long bz = blockIdx.z;
    const long long tileM = (long long)blockIdx.y * BM;
    const long long tileN = (long long)blockIdx.x * BN;
    const __half* pAh = Ah + bz * strideA + tileM * ldA;
    const __half* pBh = Bh + bz * strideB + tileN * ldB;
    const __half* pBl = (NPASS == 2) ? (Bl + bz * strideB + tileN * ldB) : nullptr;

    float acc[4][8][4];
#pragma unroll
    for (int i = 0; i < 4; i++)
#pragma unroll
        for (int j = 0; j < 8; j++)
#pragma unroll
            for (int c = 0; c < 4; c++) acc[i][j][c] = 0.f;

    const int KT = Ksz / BKt;

    // prologue: 2 of 3 stages in flight
    load_tile<NPASS>(sb + 0*STB, pAh, pBh, pBl, ldA, ldB, 0, tid);
    CP_COMMIT();
    load_tile<NPASS>(sb + 1*STB, pAh, pBh, pBl, ldA, ldB, BKt, tid);
    CP_COMMIT();

    const uint32_t aBase = (uint32_t)(wm*64 + g8 + ((quad & 1) ? 8 : 0)) * TILE_STRIDE
                         + ((quad & 2) ? 16 : 0);
    const uint32_t bBase = (uint32_t)(wn*64 + g8 + ((quad & 2) ? 8 : 0)) * TILE_STRIDE
                         + ((quad & 1) ? 16 : 0);

    int stageC = 0;
#pragma unroll 1
    for (int kt = 0; kt < KT; kt++) {
        if (kt < KT - 1) asm volatile("cp.async.wait_group 1;" ::: "memory");
        else             asm volatile("cp.async.wait_group 0;" ::: "memory");
        __syncthreads();
        const uint32_t base = sb + stageC * STB;
        if (kt + 2 < KT) {
            int stageN = stageC + 2; if (stageN >= 3) stageN -= 3;
            load_tile<NPASS>(sb + stageN * STB, pAh, pBh, pBl,
                             ldA, ldB, (kt + 2) * BKt, tid);
            CP_COMMIT();
        }
#pragma unroll
        for (int ks = 0; ks < 2; ks++) {
            uint32_t ah[4][4], bb[4][4];
#pragma unroll
            for (int i = 0; i < 4; i++)
                ldm4(ah[i], base + aBase + i * (16*TILE_STRIDE) + ks * 32);
            // pass 1: Ah * Bh
#pragma unroll
            for (int j = 0; j < 4; j++)
                ldm4(bb[j], base + SUB_BYTES + bBase + j * (16*TILE_STRIDE) + ks * 32);
#pragma unroll
            for (int i = 0; i < 4; i++)
#pragma unroll
                for (int j = 0; j < 8; j++)
                    mma16816(acc[i][j], ah[i], bb[j>>1][(j&1)*2], bb[j>>1][(j&1)*2+1]);
            if (NPASS == 2) {
                // pass 2: Ah * Bl
#pragma unroll
                for (int j = 0; j < 4; j++)
                    ldm4(bb[j], base + 2*SUB_BYTES + bBase + j * (16*TILE_STRIDE) + ks * 32);
#pragma unroll
                for (int i = 0; i < 4; i++)
#pragma unroll
                    for (int j = 0; j < 8; j++)
                        mma16816(acc[i][j], ah[i], bb[j>>1][(j&1)*2], bb[j>>1][(j&1)*2+1]);
            }
        }
        if (++stageC == 3) stageC = 0;
    }

    // ---------------- epilogue ----------------
    const long long rowBase = tileM + wm * 64;
    const long long colBase = tileN + wn * 64;
    const long long cOff = bz * strideC;
#pragma unroll
    for (int i = 0; i < 4; i++) {
#pragma unroll
        for (int j = 0; j < 8; j++) {
            long long r0 = rowBase + i * 16 + g;
            long long c0 = colBase + j * 8 + 2 * tg;
#pragma unroll
            for (int h = 0; h < 2; h++) {
                long long r = r0 + h * 8;
                float f0 = acc[i][j][2*h + 0];
                float f1 = acc[i][j][2*h + 1];
                long long off = cOff + r * ldC + c0;
                if (MODE >= 2) {
                    float2 v; v.x = f0 * scale; v.y = f1 * scale;
                    *(float2*)(outF + off) = v;
                } else {
                    if (MODE == 0) { f0 += bias[c0]; f1 += bias[c0 + 1]; }
                    else           { float bb2 = bias[r]; f0 += bb2; f1 += bb2; }
                    __half h0 = __float2half_rn(f0);
                    __half h1 = __float2half_rn(f1);
                    uint32_t hp = (uint32_t)__half_as_ushort(h0) |
                                  ((uint32_t)__half_as_ushort(h1) << 16);
                    *(uint32_t*)(outHi + off) = hp;
                    if (outLo) {
                        __half l0 = __float2half_rn(f0 - __half2float(h0));
                        __half l1 = __float2half_rn(f1 - __half2float(h1));
                        uint32_t lp = (uint32_t)__half_as_ushort(l0) |
                                      ((uint32_t)__half_as_ushort(l1) << 16);
                        *(uint32_t*)(outLo + off) = lp;
                    }
                }
            }
        }
    }
}

// ---------------- split fp32 -> fp16 hi/lo ---------------------------------
__global__ __launch_bounds__(256) void split_kernel(
    const float4* __restrict__ src, uint2* __restrict__ hi, uint2* __restrict__ lo, int n4)
{
    int i = blockIdx.x * 256 + threadIdx.x;
    if (i >= n4) return;
    float4 v = src[i];
    float f[4] = {v.x, v.y, v.z, v.w};
    uint32_t hh[2], ll[2];
#pragma unroll
    for (int j = 0; j < 2; j++) {
        __half h0 = __float2half_rn(f[2*j]);
        __half h1 = __float2half_rn(f[2*j+1]);
        __half l0 = __float2half_rn(f[2*j]   - __half2float(h0));
        __half l1 = __float2half_rn(f[2*j+1] - __half2float(h1));
        hh[j] = (uint32_t)__half_as_ushort(h0) | ((uint32_t)__half_as_ushort(h1) << 16);
        ll[j] = (uint32_t)__half_as_ushort(l0) | ((uint32_t)__half_as_ushort(l1) << 16);
    }
    hi[i] = make_uint2(hh[0], hh[1]);
    lo[i] = make_uint2(ll[0], ll[1]);
}

// ---------------- softmax rows, in-place, + fp16 hi ------------------------
__global__ __launch_bounds__(256) void softmax_split_kernel(
    float* __restrict__ att, __half* __restrict__ ahi)
{
    __shared__ float row[2048];
    __shared__ float red[8];
    const long long base = (long long)blockIdx.x * 2048;
    float* p = att + base;
    const int tid = threadIdx.x;

    float m = -3.0e38f;
    for (int i = tid; i < 2048; i += 256) { float v = p[i]; row[i] = v; m = fmaxf(m, v); }
#pragma unroll
    for (int o = 16; o > 0; o >>= 1) m = fmaxf(m, __shfl_xor_sync(0xffffffffu, m, o));
    if ((tid & 31) == 0) red[tid >> 5] = m;
    __syncthreads();
    m = red[0];
#pragma unroll
    for (int i = 1; i < 8; i++) m = fmaxf(m, red[i]);
    __syncthreads();

    float s = 0.f;
    for (int i = tid; i < 2048; i += 256) { float e = __expf(row[i] - m); row[i] = e; s += e; }
#pragma unroll
    for (int o = 16; o > 0; o >>= 1) s += __shfl_xor_sync(0xffffffffu, s, o);
    if ((tid & 31) == 0) red[tid >> 5] = s;
    __syncthreads();
    s = red[0];
#pragma unroll
    for (int i = 1; i < 8; i++) s += red[i];
    const float inv = 1.f / s;

    for (int i = tid; i < 2048; i += 256) {
        float v = row[i] * inv;
        p[i] = v;
        ahi[base + i] = __float2half_rn(v);
    }
}

// ---------------------------------------------------------------------------
extern "C" void kernel_launch(void* const* d_in, const int* in_sizes, int n_in,
                              void* d_out, int out_size)
{
    const float* X  = (const float*)d_in[0];
    const float* Wq = (const float*)d_in[1];
    const float* bq = (const float*)d_in[2];
    const float* Wk = (const float*)d_in[3];
    const float* bk = (const float*)d_in[4];
    const float* Wv = (const float*)d_in[5];
    const float* bv = (const float*)d_in[6];

    float* outp = (float*)d_out;                      // [4,2048,1024]
    float* att  = outp + 8388608ll;                   // [4,2048,2048]

    __half *Xhi, *Xlo, *Wqh, *Wql, *Wkh, *Wkl, *Wvh, *Wvl;
    __half *Qhi, *Khi, *Klo, *Vth, *Ahi;
    cudaGetSymbolAddress((void**)&Xhi, g_Xhi);  cudaGetSymbolAddress((void**)&Xlo, g_Xlo);
    cudaGetSymbolAddress((void**)&Wqh, g_Wqhi); cudaGetSymbolAddress((void**)&Wql, g_Wqlo);
    cudaGetSymbolAddress((void**)&Wkh, g_Wkhi); cudaGetSymbolAddress((void**)&Wkl, g_Wklo);
    cudaGetSymbolAddress((void**)&Wvh, g_Wvhi); cudaGetSymbolAddress((void**)&Wvl, g_Wvlo);
    cudaGetSymbolAddress((void**)&Qhi, g_Qhi);
    cudaGetSymbolAddress((void**)&Khi, g_Khi);  cudaGetSymbolAddress((void**)&Klo, g_Klo);
    cudaGetSymbolAddress((void**)&Vth, g_Vthi);
    cudaGetSymbolAddress((void**)&Ahi, g_AThi);

    cudaFuncSetAttribute((const void*)mm_kernel<0,2>, cudaFuncAttributeMaxDynamicSharedMemorySize, SMEM_P2);
    cudaFuncSetAttribute((const void*)mm_kernel<1,2>, cudaFuncAttributeMaxDynamicSharedMemorySize, SMEM_P2);
    cudaFuncSetAttribute((const void*)mm_kernel<2,2>, cudaFuncAttributeMaxDynamicSharedMemorySize, SMEM_P2);
    cudaFuncSetAttribute((const void*)mm_kernel<3,1>, cudaFuncAttributeMaxDynamicSharedMemorySize, SMEM_P1);

    const cudaStream_t s0 = 0;
    const cudaStream_t sK = gsK;   // zero-init fallback = default stream (serial, correct)
    const cudaStream_t sV = gsV;
    const cudaStream_t s3 = gs3;

    const long long sQK = 2097152ll;   // per-batch Q/K elements
    const long long sNN = 4194304ll;   // per-batch att elements

    // ---- main stream: split X, then fork ----
    split_kernel<<<8192, 256, 0, s0>>>((const float4*)X, (uint2*)Xhi, (uint2*)Xlo, 2097152);
    cudaEventRecord(geX, s0);

    // ---- branch K ----
    cudaStreamWaitEvent(sK, geX, 0);
    split_kernel<<<1024, 256, 0, sK>>>((const float4*)Wk, (uint2*)Wkh, (uint2*)Wkl, 262144);
    mm_kernel<0,2><<<dim3(8, 64, 1), 128, SMEM_P2, sK>>>(
        Xhi, 1024, 0, Wkh, Wkl, 1024, 0, bk,
        nullptr, Khi, Klo, 1024, 0, 1024, 1.f);
    cudaEventRecord(geK, sK);

    // ---- branch V ----
    cudaStreamWaitEvent(sV, geX, 0);
    split_kernel<<<1024, 256, 0, sV>>>((const float4*)Wv, (uint2*)Wvh, (uint2*)Wvl, 262144);
    mm_kernel<1,2><<<dim3(64, 8, 1), 128, SMEM_P2, sV>>>(
        Wvh, 1024, 0, Xhi, Xlo, 1024, 0, bv,
        nullptr, Vth, nullptr, 8192, 0, 1024, 1.f);
    cudaEventRecord(geV, sV);

    // ---- main stream: Q proj ----
    split_kernel<<<1024, 256, 0, s0>>>((const float4*)Wq, (uint2*)Wqh, (uint2*)Wql, 262144);
    mm_kernel<0,2><<<dim3(8, 64, 1), 128, SMEM_P2, s0>>>(
        Xhi, 1024, 0, Wqh, Wql, 1024, 0, bq,
        nullptr, Qhi, nullptr, 1024, 0, 1024, 1.f);
    cudaEventRecord(geQ, s0);

    // ---- per-batch chains: scores(b) -> softmax(b) -> AV(b) ----
    // batch 0 on s0, 1 on sK, 2 on sV, 3 on s3
    {
        // b = 0 (s0 already ordered after Qproj)
        cudaStreamWaitEvent(s0, geK, 0);
        mm_kernel<2,2><<<dim3(16, 16, 1), 128, SMEM_P2, s0>>>(
            Qhi, 1024, 0, Khi, Klo, 1024, 0, nullptr,
            att, nullptr, nullptr, 2048, 0, 1024, SCALE_);
        softmax_split_kernel<<<2048, 256, 0, s0>>>(att, Ahi);
        cudaStreamWaitEvent(s0, geV, 0);
        mm_kernel<3,1><<<dim3(8, 16, 1), 128, SMEM_P1, s0>>>(
            Ahi, 2048, 0, Vth, nullptr, 8192, 0, nullptr,
            outp, nullptr, nullptr, 1024, 0, 2048, 1.f);
    }
    {
        // b = 1 on sK (already ordered after Kproj)
        cudaStreamWaitEvent(sK, geQ, 0);
        mm_kernel<2,2><<<dim3(16, 16, 1), 128, SMEM_P2, sK>>>(
            Qhi + 1*sQK, 1024, 0, Khi + 1*sQK, Klo + 1*sQK, 1024, 0, nullptr,
            att + 1*sNN, nullptr, nullptr, 2048, 0, 1024, SCALE_);
        softmax_split_kernel<<<2048, 256, 0, sK>>>(att + 1*sNN, Ahi + 1*sNN);
        cudaStreamWaitEvent(sK, geV, 0);
        mm_kernel<3,1><<<dim3(8, 16, 1), 128, SMEM_P1, sK>>>(
            Ahi + 1*sNN, 2048, 0, Vth + 1*2048, nullptr, 8192, 0, nullptr,
            outp + 1*sQK, nullptr, nullptr, 1024, 0, 2048, 1.f);
        cudaEventRecord(geB1, sK);
    }
    {
        // b = 2 on sV (already ordered after Vproj)
        cudaStreamWaitEvent(sV, geQ, 0);
        cudaStreamWaitEvent(sV, geK, 0);
        mm_kernel<2,2><<<dim3(16, 16, 1), 128, SMEM_P2, sV>>>(
            Qhi + 2*sQK, 1024, 0, Khi + 2*sQK, Klo + 2*sQK, 1024, 0, nullptr,
            att + 2*sNN, nullptr, nullptr, 2048, 0, 1024, SCALE_);
        softmax_split_kernel<<<2048, 256, 0, sV>>>(att + 2*sNN, Ahi + 2*sNN);
        mm_kernel<3,1><<<dim3(8, 16, 1), 128, SMEM_P1, sV>>>(
            Ahi + 2*sNN, 2048, 0, Vth + 2*2048, nullptr, 8192, 0, nullptr,
            outp + 2*sQK, nullptr, nullptr, 1024, 0, 2048, 1.f);
        cudaEventRecord(geB2, sV);
    }
    {
        // b = 3 on s3
        cudaStreamWaitEvent(s3, geQ, 0);
        cudaStreamWaitEvent(s3, geK, 0);
        mm_kernel<2,2><<<dim3(16, 16, 1), 128, SMEM_P2, s3>>>(
            Qhi + 3*sQK, 1024, 0, Khi + 3*sQK, Klo + 3*sQK, 1024, 0, nullptr,
            att + 3*sNN, nullptr, nullptr, 2048, 0, 1024, SCALE_);
        softmax_split_kernel<<<2048, 256, 0, s3>>>(att + 3*sNN, Ahi + 3*sNN);
        cudaStreamWaitEvent(s3, geV, 0);
        mm_kernel<3,1><<<dim3(8, 16, 1), 128, SMEM_P1, s3>>>(
            Ahi + 3*sNN, 2048, 0, Vth + 3*2048, nullptr, 8192, 0, nullptr,
            outp + 3*sQK, nullptr, nullptr, 1024, 0, 2048, 1.f);
        cudaEventRecord(geB3, s3);
    }

    // ---- join all branches back into the origin stream ----
    cudaStreamWaitEvent(s0, geB1, 0);
    cudaStreamWaitEvent(s0, geB2, 0);
    cudaStreamWaitEvent(s0, geB3, 0);
}